// round 16
// baseline (speedup 1.0000x reference)
#include <cuda_runtime.h>
#include <cuda_bf16.h>
#include <cstdint>
#include <math.h>

// Problem constants
#define BB   2
#define SS   2048
#define HH   1024
#define NH   16
#define HD   64
#define MTOT (BB*SS)   // 4096

// Scratch (device globals: allocation-free per harness rules)
// bf16 split pairs
__device__ __nv_bfloat16 g_Qhi[BB*NH*SS*HD];  // [B,nh,S,hd]
__device__ __nv_bfloat16 g_Qlo[BB*NH*SS*HD];
__device__ __nv_bfloat16 g_Khi[BB*NH*SS*HD];
__device__ __nv_bfloat16 g_Klo[BB*NH*SS*HD];
__device__ __nv_bfloat16 g_Vhi[BB*NH*SS*HD];
__device__ __nv_bfloat16 g_Vlo[BB*NH*SS*HD];
__device__ __nv_bfloat16 g_Ahi[MTOT*HH];      // GEMM A staging ([MTOT,HH])
__device__ __nv_bfloat16 g_Alo[MTOT*HH];
__device__ __nv_bfloat16 g_Whi[HH*HH];
__device__ __nv_bfloat16 g_Wlo[HH*HH];

// ---------------------------------------------------------------------------
// PTX helpers
// ---------------------------------------------------------------------------
__device__ __forceinline__ void cp16(unsigned dst, const void* src) {
    asm volatile("cp.async.cg.shared.global [%0], [%1], 16;"
                 :: "r"(dst), "l"(src));
}

__device__ __forceinline__ void cp_commit_wait() {
    asm volatile("cp.async.commit_group;");
    asm volatile("cp.async.wait_group 0;");
}

__device__ __forceinline__ void ldsm4(unsigned (&r)[4], unsigned addr) {
    asm volatile("ldmatrix.sync.aligned.m8n8.x4.shared.b16 {%0,%1,%2,%3}, [%4];"
                 : "=r"(r[0]), "=r"(r[1]), "=r"(r[2]), "=r"(r[3]) : "r"(addr));
}

__device__ __forceinline__ void ldsm4t(unsigned (&r)[4], unsigned addr) {
    asm volatile("ldmatrix.sync.aligned.m8n8.x4.trans.shared.b16 {%0,%1,%2,%3}, [%4];"
                 : "=r"(r[0]), "=r"(r[1]), "=r"(r[2]), "=r"(r[3]) : "r"(addr));
}

__device__ __forceinline__ void mma16816(float (&c)[4], const unsigned (&a)[4],
                                         unsigned b0, unsigned b1) {
    asm volatile("mma.sync.aligned.m16n8k16.row.col.f32.bf16.bf16.f32 "
                 "{%0,%1,%2,%3},{%4,%5,%6,%7},{%8,%9},{%0,%1,%2,%3};"
                 : "+f"(c[0]), "+f"(c[1]), "+f"(c[2]), "+f"(c[3])
                 : "r"(a[0]), "r"(a[1]), "r"(a[2]), "r"(a[3]), "r"(b0), "r"(b1));
}

// fp32 pair -> packed bf16x2 (round-nearest)
__device__ __forceinline__ unsigned pack_bf(float x, float y) {
    __nv_bfloat162 t = __float22bfloat162_rn(make_float2(x, y));
    return *(unsigned*)&t;
}

// ---------------------------------------------------------------------------
// fp32 -> (bf16 hi, bf16 lo) split (for the raw inputs and weights).
// ---------------------------------------------------------------------------
__global__ void cvt_split_kernel(const float* __restrict__ x,
                                 __nv_bfloat16* __restrict__ hi,
                                 __nv_bfloat16* __restrict__ lo)
{
    int i = blockIdx.x * blockDim.x + threadIdx.x;   // float4 index
    float4 v = ((const float4*)x)[i];

    __nv_bfloat16 h0 = __float2bfloat16(v.x);
    __nv_bfloat16 h1 = __float2bfloat16(v.y);
    __nv_bfloat16 h2 = __float2bfloat16(v.z);
    __nv_bfloat16 h3 = __float2bfloat16(v.w);
    __nv_bfloat16 l0 = __float2bfloat16(v.x - __bfloat162float(h0));
    __nv_bfloat16 l1 = __float2bfloat16(v.y - __bfloat162float(h1));
    __nv_bfloat16 l2 = __float2bfloat16(v.z - __bfloat162float(h2));
    __nv_bfloat16 l3 = __float2bfloat16(v.w - __bfloat162float(h3));

    __nv_bfloat162* hp = (__nv_bfloat162*)hi;
    __nv_bfloat162* lp = (__nv_bfloat162*)lo;
    hp[2*i]   = __nv_bfloat162(h0, h1);
    hp[2*i+1] = __nv_bfloat162(h2, h3);
    lp[2*i]   = __nv_bfloat162(l0, l1);
    lp[2*i+1] = __nv_bfloat162(l2, l3);
}

// ---------------------------------------------------------------------------
// Tensor-core NT GEMM via bf16 split: C[m,n] = sum_k A[m,k]*W[n,k] + bias[n]
// MODE 0: C fp32 row-major [MTOT,HH] (final output).
// MODE 1: C written as bf16 hi/lo pair to [B,nh,S,hd] split-head layout.
// ---------------------------------------------------------------------------
template<int MODE>
__global__ __launch_bounds__(256, 2)
void gemm_mma_kernel(const __nv_bfloat16* __restrict__ Ahi,
                     const __nv_bfloat16* __restrict__ Alo,
                     const __nv_bfloat16* __restrict__ Whi,
                     const __nv_bfloat16* __restrict__ Wlo,
                     const float* __restrict__ bias,
                     float* __restrict__ C,
                     __nv_bfloat16* __restrict__ Chi,
                     __nv_bfloat16* __restrict__ Clo)
{
    __shared__ __align__(128) char sm[49152];
    const unsigned sbase = (unsigned)__cvta_generic_to_shared(sm);
    const unsigned sAhi = sbase;
    const unsigned sAlo = sbase + 16384;
    const unsigned sBhi = sbase + 32768;
    const unsigned sBlo = sbase + 40960;

    const int tid  = threadIdx.x;
    const int lane = tid & 31;
    const int warp = tid >> 5;
    const int wm0  = (warp >> 1) * 32;
    const int wn0  = (warp & 1) * 32;
    const int m0   = blockIdx.y * 128;
    const int n0   = blockIdx.x * 64;

    float acc[2][4][4] = {};

    const int a_r   = lane & 15;
    const int a_kh  = lane >> 4;
    const int b_r   = (lane & 7) + ((lane >> 4) << 3);
    const int b_kh  = (lane >> 3) & 1;

    for (int k0 = 0; k0 < HH; k0 += 64) {
        __syncthreads();
        #pragma unroll
        for (int i = 0; i < 4; i++) {
            int e = tid + i * 256;
            int r = e >> 3, c = e & 7;
            unsigned soff = (unsigned)(r * 128 + ((c ^ (r & 7)) << 4));
            cp16(sAhi + soff, Ahi + (size_t)(m0 + r) * HH + k0 + c * 8);
            cp16(sAlo + soff, Alo + (size_t)(m0 + r) * HH + k0 + c * 8);
        }
        #pragma unroll
        for (int i = 0; i < 2; i++) {
            int e = tid + i * 256;
            int r = e >> 3, c = e & 7;
            unsigned soff = (unsigned)(r * 128 + ((c ^ (r & 7)) << 4));
            cp16(sBhi + soff, Whi + (size_t)(n0 + r) * HH + k0 + c * 8);
            cp16(sBlo + soff, Wlo + (size_t)(n0 + r) * HH + k0 + c * 8);
        }
        cp_commit_wait();
        __syncthreads();

        #pragma unroll
        for (int kk = 0; kk < 4; kk++) {
            unsigned fAh[2][4], fAl[2][4], fBh[2][4], fBl[2][4];
            #pragma unroll
            for (int mt = 0; mt < 2; mt++) {
                int r = wm0 + mt * 16 + a_r;
                int c = kk * 2 + a_kh;
                unsigned off = (unsigned)(r * 128 + ((c ^ (r & 7)) << 4));
                ldsm4(fAh[mt], sAhi + off);
                ldsm4(fAl[mt], sAlo + off);
            }
            #pragma unroll
            for (int nt2 = 0; nt2 < 2; nt2++) {
                int r = wn0 + nt2 * 16 + b_r;
                int c = kk * 2 + b_kh;
                unsigned off = (unsigned)(r * 128 + ((c ^ (r & 7)) << 4));
                ldsm4(fBh[nt2], sBhi + off);
                ldsm4(fBl[nt2], sBlo + off);
            }
            #pragma unroll
            for (int mt = 0; mt < 2; mt++) {
                #pragma unroll
                for (int nt = 0; nt < 4; nt++) {
                    int n2 = nt >> 1, p = (nt & 1) * 2;
                    mma16816(acc[mt][nt], fAh[mt], fBh[n2][p], fBh[n2][p+1]);
                    mma16816(acc[mt][nt], fAh[mt], fBl[n2][p], fBl[n2][p+1]);
                    mma16816(acc[mt][nt], fAl[mt], fBh[n2][p], fBh[n2][p+1]);
                }
            }
        }
    }

    const int g = lane >> 2, q = lane & 3;
    #pragma unroll
    for (int mt = 0; mt < 2; mt++) {
        #pragma unroll
        for (int nt = 0; nt < 4; nt++) {
            int col = n0 + wn0 + nt * 8 + q * 2;
            float b0 = bias[col], b1 = bias[col + 1];
            #pragma unroll
            for (int half = 0; half < 2; half++) {
                int row = m0 + wm0 + mt * 16 + g + half * 8;
                float v0 = acc[mt][nt][half * 2]     + b0;
                float v1 = acc[mt][nt][half * 2 + 1] + b1;
                if (MODE == 0) {
                    *(float2*)&C[(size_t)row * HH + col] = make_float2(v0, v1);
                } else {
                    int b = row >> 11, s = row & 2047;
                    int h = col >> 6,  d = col & 63;
                    size_t idx = (((size_t)(b * NH + h)) * SS + s) * HD + d;
                    __nv_bfloat162 hh = __float22bfloat162_rn(make_float2(v0, v1));
                    *(__nv_bfloat162*)&Chi[idx] = hh;
                    __nv_bfloat162 ll = __float22bfloat162_rn(make_float2(
                        v0 - __bfloat162float(hh.x), v1 - __bfloat162float(hh.y)));
                    *(__nv_bfloat162*)&Clo[idx] = ll;
                }
            }
        }
    }
}

// ---------------------------------------------------------------------------
// HMMA flash attention (bf16 split, fp32 softmax/accum).
// Block: 256 threads (8 warps), q-tile 128 (m16/warp), kt tiles of 64 seq.
// smem 32KB union: Q-stage (hi|lo 16K each) then per-kt K/V hi/lo 8K each.
// Epilogue writes O as bf16 hi/lo into g_Ahi/g_Alo ([B,S,H] row-major).
// ---------------------------------------------------------------------------
__global__ __launch_bounds__(256)
void attn_mma_kernel()
{
    __shared__ __align__(128) char sm[32768];
    const unsigned sbase = (unsigned)__cvta_generic_to_shared(sm);

    const int tid  = threadIdx.x;
    const int lane = tid & 31;
    const int w    = tid >> 5;          // 0..7
    const int qt   = blockIdx.x;        // 0..15 (q tiles of 128)
    const int bh   = blockIdx.y;        // 0..31
    const size_t head_base = (size_t)bh * SS * HD;

    // ---- Stage Q tile (128 x 64 hi/lo) and pull fragments into registers
    {
        const __nv_bfloat16* Qh = g_Qhi + head_base + (size_t)qt * 128 * HD;
        const __nv_bfloat16* Ql = g_Qlo + head_base + (size_t)qt * 128 * HD;
        #pragma unroll
        for (int i = 0; i < 4; i++) {
            int e = tid + i * 256;
            int r = e >> 3, c = e & 7;
            unsigned soff = (unsigned)(r * 128 + ((c ^ (r & 7)) << 4));
            cp16(sbase + soff,         Qh + (size_t)r * HD + c * 8);
            cp16(sbase + 16384 + soff, Ql + (size_t)r * HD + c * 8);
        }
        cp_commit_wait();
        __syncthreads();
    }

    const int a_r  = lane & 15;
    const int a_kh = lane >> 4;
    unsigned qh[4][4], ql[4][4];
    #pragma unroll
    for (int ks = 0; ks < 4; ks++) {
        int r = w * 16 + a_r;
        int c = ks * 2 + a_kh;
        unsigned off = (unsigned)(r * 128 + ((c ^ (r & 7)) << 4));
        ldsm4(qh[ks], sbase + off);
        ldsm4(ql[ks], sbase + 16384 + off);
    }

    float o[8][4] = {};                  // [d-tile nt][frag]: rows g,g+8 / cols 2q,2q+1
    float mrow[2] = {-1e30f, -1e30f};
    float lrow[2] = {0.0f, 0.0f};

    const unsigned sKhi = sbase;
    const unsigned sKlo = sbase + 8192;
    const unsigned sVhi = sbase + 16384;
    const unsigned sVlo = sbase + 24576;
    const int b_r  = (lane & 7) + ((lane >> 4) << 3);
    const int b_kh = (lane >> 3) & 1;

    for (int kt = 0; kt < SS / 64; kt++) {
        __syncthreads();                 // Q-frag loads / previous tile reads done
        const size_t tb = head_base + (size_t)kt * 64 * HD;
        #pragma unroll
        for (int i = 0; i < 2; i++) {
            int e = tid + i * 256;
            int r = e >> 3, c = e & 7;
            unsigned soff = (unsigned)(r * 128 + ((c ^ (r & 7)) << 4));
            size_t gi = tb + (size_t)r * HD + c * 8;
            cp16(sKhi + soff, g_Khi + gi);
            cp16(sKlo + soff, g_Klo + gi);
            cp16(sVhi + soff, g_Vhi + gi);
            cp16(sVlo + soff, g_Vlo + gi);
        }
        cp_commit_wait();
        __syncthreads();

        // ---- S = Q K^T (m16 x n64), bf16 split 3-pass, fp32 accum
        float sc[8][4] = {};
        #pragma unroll
        for (int ks = 0; ks < 4; ks++) {
            unsigned kh[4][4], kl[4][4];
            #pragma unroll
            for (int nt2 = 0; nt2 < 4; nt2++) {
                int r = nt2 * 16 + b_r;
                int c = ks * 2 + b_kh;
                unsigned off = (unsigned)(r * 128 + ((c ^ (r & 7)) << 4));
                ldsm4(kh[nt2], sKhi + off);
                ldsm4(kl[nt2], sKlo + off);
            }
            #pragma unroll
            for (int nt = 0; nt < 8; nt++) {
                int n2 = nt >> 1, p = (nt & 1) * 2;
                mma16816(sc[nt], qh[ks], kh[n2][p], kh[n2][p+1]);
                mma16816(sc[nt], qh[ks], kl[n2][p], kl[n2][p+1]);
                mma16816(sc[nt], ql[ks], kh[n2][p], kh[n2][p+1]);
            }
        }

        // ---- online softmax on fragment rows (g and g+8)
        #pragma unroll
        for (int rr = 0; rr < 2; rr++) {
            const int base = rr * 2;
            float tm = -1e30f;
            #pragma unroll
            for (int nt = 0; nt < 8; nt++) {
                sc[nt][base]     *= 0.125f;     // 1/sqrt(64)
                sc[nt][base + 1] *= 0.125f;
                tm = fmaxf(tm, fmaxf(sc[nt][base], sc[nt][base + 1]));
            }
            tm = fmaxf(tm, __shfl_xor_sync(0xffffffffu, tm, 1));
            tm = fmaxf(tm, __shfl_xor_sync(0xffffffffu, tm, 2));
            float mn   = fmaxf(mrow[rr], tm);
            float corr = __expf(mrow[rr] - mn);
            mrow[rr] = mn;
            float rs = 0.0f;
            #pragma unroll
            for (int nt = 0; nt < 8; nt++) {
                float p0 = __expf(sc[nt][base]     - mn);
                float p1 = __expf(sc[nt][base + 1] - mn);
                sc[nt][base] = p0; sc[nt][base + 1] = p1;
                rs += p0 + p1;
            }
            rs += __shfl_xor_sync(0xffffffffu, rs, 1);
            rs += __shfl_xor_sync(0xffffffffu, rs, 2);
            lrow[rr] = lrow[rr] * corr + rs;
            #pragma unroll
            for (int nt = 0; nt < 8; nt++) {
                o[nt][base]     *= corr;
                o[nt][base + 1] *= corr;
            }
        }

        // ---- O += P V  (P from S-fragments, split hi/lo; V via ldmatrix.trans)
        #pragma unroll
        for (int ks2 = 0; ks2 < 4; ks2++) {
            unsigned phi[4], plo[4];
            #pragma unroll
            for (int part = 0; part < 2; part++) {
                int nt = 2 * ks2 + part;
                #pragma unroll
                for (int hh = 0; hh < 2; hh++) {
                    float p0 = sc[nt][hh * 2], p1 = sc[nt][hh * 2 + 1];
                    __nv_bfloat162 h2 = __float22bfloat162_rn(make_float2(p0, p1));
                    phi[part * 2 + hh] = *(unsigned*)&h2;
                    plo[part * 2 + hh] = pack_bf(p0 - __bfloat162float(h2.x),
                                                 p1 - __bfloat162float(h2.y));
                }
            }
            #pragma unroll
            for (int dt = 0; dt < 4; dt++) {
                int r = ks2 * 16 + (lane & 15);
                int c = dt * 2 + (lane >> 4);
                unsigned off = (unsigned)(r * 128 + ((c ^ (r & 7)) << 4));
                unsigned vh[4], vl[4];
                ldsm4t(vh, sVhi + off);
                ldsm4t(vl, sVlo + off);
                mma16816(o[2*dt],     phi, vh[0], vh[1]);
                mma16816(o[2*dt],     phi, vl[0], vl[1]);
                mma16816(o[2*dt],     plo, vh[0], vh[1]);
                mma16816(o[2*dt + 1], phi, vh[2], vh[3]);
                mma16816(o[2*dt + 1], phi, vl[2], vl[3]);
                mma16816(o[2*dt + 1], plo, vh[2], vh[3]);
            }
        }
    }

    // ---- epilogue: normalize, write bf16 hi/lo into GEMM-A staging [B,S,H]
    const int b = bh >> 4, h = bh & 15;
    const int g = lane >> 2, q = lane & 3;
    const float inv0 = 1.0f / lrow[0];
    const float inv1 = 1.0f / lrow[1];
    const int row0 = qt * 128 + w * 16 + g;
    #pragma unroll
    for (int nt = 0; nt < 8; nt++) {
        int d = h * 64 + nt * 8 + q * 2;
        size_t i0 = ((size_t)(b * SS + row0))     * HH + d;
        size_t i1 = ((size_t)(b * SS + row0 + 8)) * HH + d;
        float v0 = o[nt][0] * inv0, v1 = o[nt][1] * inv0;
        float v2 = o[nt][2] * inv1, v3 = o[nt][3] * inv1;
        __nv_bfloat162 h2a = __float22bfloat162_rn(make_float2(v0, v1));
        *(__nv_bfloat162*)&g_Ahi[i0] = h2a;
        *(__nv_bfloat162*)&g_Alo[i0] = __float22bfloat162_rn(make_float2(
            v0 - __bfloat162float(h2a.x), v1 - __bfloat162float(h2a.y)));
        __nv_bfloat162 h2b = __float22bfloat162_rn(make_float2(v2, v3));
        *(__nv_bfloat162*)&g_Ahi[i1] = h2b;
        *(__nv_bfloat162*)&g_Alo[i1] = __float22bfloat162_rn(make_float2(
            v2 - __bfloat162float(h2b.x), v3 - __bfloat162float(h2b.y)));
    }
}

// ---------------------------------------------------------------------------
extern "C" void kernel_launch(void* const* d_in, const int* in_sizes, int n_in,
                              void* d_out, int out_size)
{
    const float* q  = (const float*)d_in[0];
    const float* k  = (const float*)d_in[1];
    const float* v  = (const float*)d_in[2];
    const float* Wq = (const float*)d_in[3];
    const float* bq = (const float*)d_in[4];
    const float* Wk = (const float*)d_in[5];
    const float* bk = (const float*)d_in[6];
    const float* Wv = (const float*)d_in[7];
    const float* bv = (const float*)d_in[8];
    const float* Wo = (const float*)d_in[9];
    const float* bo = (const float*)d_in[10];
    float* out = (float*)d_out;

    __nv_bfloat16 *Qhi, *Qlo, *Khi, *Klo, *Vhi, *Vlo, *Ahi, *Alo, *Whi, *Wlo;
    cudaGetSymbolAddress((void**)&Qhi, g_Qhi);
    cudaGetSymbolAddress((void**)&Qlo, g_Qlo);
    cudaGetSymbolAddress((void**)&Khi, g_Khi);
    cudaGetSymbolAddress((void**)&Klo, g_Klo);
    cudaGetSymbolAddress((void**)&Vhi, g_Vhi);
    cudaGetSymbolAddress((void**)&Vlo, g_Vlo);
    cudaGetSymbolAddress((void**)&Ahi, g_Ahi);
    cudaGetSymbolAddress((void**)&Alo, g_Alo);
    cudaGetSymbolAddress((void**)&Whi, g_Whi);
    cudaGetSymbolAddress((void**)&Wlo, g_Wlo);

    const int CVT_A_BLOCKS = (MTOT * HH / 4) / 256;  // 4096
    const int CVT_W_BLOCKS = (HH * HH / 4) / 256;    // 1024
    dim3 blk(256);
    dim3 gg(HH / 64, MTOT / 128);                    // (16, 32)

    // Q projection -> bf16 split heads
    cvt_split_kernel<<<CVT_A_BLOCKS, blk>>>(q, Ahi, Alo);
    cvt_split_kernel<<<CVT_W_BLOCKS, blk>>>(Wq, Whi, Wlo);
    gemm_mma_kernel<1><<<gg, blk>>>(Ahi, Alo, Whi, Wlo, bq, nullptr, Qhi, Qlo);
    // K projection
    cvt_split_kernel<<<CVT_A_BLOCKS, blk>>>(k, Ahi, Alo);
    cvt_split_kernel<<<CVT_W_BLOCKS, blk>>>(Wk, Whi, Wlo);
    gemm_mma_kernel<1><<<gg, blk>>>(Ahi, Alo, Whi, Wlo, bk, nullptr, Khi, Klo);
    // V projection
    cvt_split_kernel<<<CVT_A_BLOCKS, blk>>>(v, Ahi, Alo);
    cvt_split_kernel<<<CVT_W_BLOCKS, blk>>>(Wv, Whi, Wlo);
    gemm_mma_kernel<1><<<gg, blk>>>(Ahi, Alo, Whi, Wlo, bv, nullptr, Vhi, Vlo);
    // Attention (writes O as bf16 split directly into Ahi/Alo)
    attn_mma_kernel<<<dim3(SS / 128, BB * NH), blk>>>();
    // Output projection
    cvt_split_kernel<<<CVT_W_BLOCKS, blk>>>(Wo, Whi, Wlo);
    gemm_mma_kernel<0><<<gg, blk>>>(Ahi, Alo, Whi, Wlo, bo, out, nullptr, nullptr);
}

// round 17
// speedup vs baseline: 1.0255x; 1.0255x over previous
#include <cuda_runtime.h>
#include <cuda_bf16.h>
#include <cstdint>
#include <math.h>

// Problem constants
#define BB   2
#define SS   2048
#define HH   1024
#define NH   16
#define HD   64
#define MTOT (BB*SS)   // 4096

// Scratch (device globals: allocation-free per harness rules)
__device__ __nv_bfloat16 g_Qhi[BB*NH*SS*HD];  // [B,nh,S,hd]
__device__ __nv_bfloat16 g_Qlo[BB*NH*SS*HD];
__device__ __nv_bfloat16 g_Khi[BB*NH*SS*HD];
__device__ __nv_bfloat16 g_Klo[BB*NH*SS*HD];
__device__ __nv_bfloat16 g_Vhi[BB*NH*SS*HD];
__device__ __nv_bfloat16 g_Vlo[BB*NH*SS*HD];
__device__ __nv_bfloat16 g_Ahi[MTOT*HH];      // GEMM A staging ([MTOT,HH])
__device__ __nv_bfloat16 g_Alo[MTOT*HH];
__device__ __nv_bfloat16 g_Whi[HH*HH];
__device__ __nv_bfloat16 g_Wlo[HH*HH];

// ---------------------------------------------------------------------------
// PTX helpers
// ---------------------------------------------------------------------------
__device__ __forceinline__ void cp16(unsigned dst, const void* src) {
    asm volatile("cp.async.cg.shared.global [%0], [%1], 16;"
                 :: "r"(dst), "l"(src));
}

__device__ __forceinline__ void cp_commit() {
    asm volatile("cp.async.commit_group;");
}

template<int N>
__device__ __forceinline__ void cp_wait() {
    asm volatile("cp.async.wait_group %0;" :: "n"(N));
}

__device__ __forceinline__ void ldsm4(unsigned (&r)[4], unsigned addr) {
    asm volatile("ldmatrix.sync.aligned.m8n8.x4.shared.b16 {%0,%1,%2,%3}, [%4];"
                 : "=r"(r[0]), "=r"(r[1]), "=r"(r[2]), "=r"(r[3]) : "r"(addr));
}

__device__ __forceinline__ void ldsm4t(unsigned (&r)[4], unsigned addr) {
    asm volatile("ldmatrix.sync.aligned.m8n8.x4.trans.shared.b16 {%0,%1,%2,%3}, [%4];"
                 : "=r"(r[0]), "=r"(r[1]), "=r"(r[2]), "=r"(r[3]) : "r"(addr));
}

__device__ __forceinline__ void mma16816(float (&c)[4], const unsigned (&a)[4],
                                         unsigned b0, unsigned b1) {
    asm volatile("mma.sync.aligned.m16n8k16.row.col.f32.bf16.bf16.f32 "
                 "{%0,%1,%2,%3},{%4,%5,%6,%7},{%8,%9},{%0,%1,%2,%3};"
                 : "+f"(c[0]), "+f"(c[1]), "+f"(c[2]), "+f"(c[3])
                 : "r"(a[0]), "r"(a[1]), "r"(a[2]), "r"(a[3]), "r"(b0), "r"(b1));
}

__device__ __forceinline__ unsigned pack_bf(float x, float y) {
    __nv_bfloat162 t = __float22bfloat162_rn(make_float2(x, y));
    return *(unsigned*)&t;
}

// ---------------------------------------------------------------------------
// fp32 -> (bf16 hi, bf16 lo) split (for the raw inputs and weights).
// ---------------------------------------------------------------------------
__global__ void cvt_split_kernel(const float* __restrict__ x,
                                 __nv_bfloat16* __restrict__ hi,
                                 __nv_bfloat16* __restrict__ lo)
{
    int i = blockIdx.x * blockDim.x + threadIdx.x;   // float4 index
    float4 v = ((const float4*)x)[i];

    __nv_bfloat16 h0 = __float2bfloat16(v.x);
    __nv_bfloat16 h1 = __float2bfloat16(v.y);
    __nv_bfloat16 h2 = __float2bfloat16(v.z);
    __nv_bfloat16 h3 = __float2bfloat16(v.w);
    __nv_bfloat16 l0 = __float2bfloat16(v.x - __bfloat162float(h0));
    __nv_bfloat16 l1 = __float2bfloat16(v.y - __bfloat162float(h1));
    __nv_bfloat16 l2 = __float2bfloat16(v.z - __bfloat162float(h2));
    __nv_bfloat16 l3 = __float2bfloat16(v.w - __bfloat162float(h3));

    __nv_bfloat162* hp = (__nv_bfloat162*)hi;
    __nv_bfloat162* lp = (__nv_bfloat162*)lo;
    hp[2*i]   = __nv_bfloat162(h0, h1);
    hp[2*i+1] = __nv_bfloat162(h2, h3);
    lp[2*i]   = __nv_bfloat162(l0, l1);
    lp[2*i+1] = __nv_bfloat162(l2, l3);
}

// ---------------------------------------------------------------------------
// Tensor-core NT GEMM, bf16 split, 2-stage cp.async pipeline.
// K-chunk 32; smem row = 128B = [hi 32 bf16 | lo 32 bf16], XOR swizzle.
// Stage: A 16K (128 rows) + B 8K (64 rows) = 24K; two stages in 48K.
// MODE 0: C fp32 row-major.  MODE 1: bf16 hi/lo split-head, scaled by oscale.
// ---------------------------------------------------------------------------
template<int MODE>
__global__ __launch_bounds__(256, 2)
void gemm_mma_kernel(const __nv_bfloat16* __restrict__ Ahi,
                     const __nv_bfloat16* __restrict__ Alo,
                     const __nv_bfloat16* __restrict__ Whi,
                     const __nv_bfloat16* __restrict__ Wlo,
                     const float* __restrict__ bias,
                     float* __restrict__ C,
                     __nv_bfloat16* __restrict__ Chi,
                     __nv_bfloat16* __restrict__ Clo,
                     float oscale)
{
    __shared__ __align__(128) char sm[49152];
    const unsigned sbase = (unsigned)__cvta_generic_to_shared(sm);
    // stage s: A at s*24576, B at s*24576 + 16384

    const int tid  = threadIdx.x;
    const int lane = tid & 31;
    const int warp = tid >> 5;
    const int wm0  = (warp >> 1) * 32;
    const int wn0  = (warp & 1) * 32;
    const int m0   = blockIdx.y * 128;
    const int n0   = blockIdx.x * 64;

    float acc[2][4][4] = {};

    const int a_r   = lane & 15;
    const int a_kh  = lane >> 4;
    const int b_r   = (lane & 7) + ((lane >> 4) << 3);
    const int b_kh  = (lane >> 3) & 1;

    // per-thread load mapping (constant over chunks)
    // A: 1024 granules (4/thread), B: 512 granules (2/thread)
    const int NCH = HH / 32;   // 32 chunks

    // ---- prologue: load chunk 0 into stage 0
    {
        const int k0 = 0;
        #pragma unroll
        for (int i = 0; i < 4; i++) {
            int e = tid + i * 256;
            int r = e >> 3, g = e & 7;
            unsigned soff = (unsigned)(r * 128 + ((g ^ (r & 7)) << 4));
            const __nv_bfloat16* base = (g < 4) ? Ahi : Alo;
            cp16(sbase + soff, base + (size_t)(m0 + r) * HH + k0 + (g & 3) * 8);
        }
        #pragma unroll
        for (int i = 0; i < 2; i++) {
            int e = tid + i * 256;
            int r = e >> 3, g = e & 7;
            unsigned soff = (unsigned)(r * 128 + ((g ^ (r & 7)) << 4));
            const __nv_bfloat16* base = (g < 4) ? Whi : Wlo;
            cp16(sbase + 16384 + soff, base + (size_t)(n0 + r) * HH + k0 + (g & 3) * 8);
        }
        cp_commit();
    }

    for (int s = 0; s < NCH; s++) {
        // issue loads for chunk s+1 into the other stage
        if (s + 1 < NCH) {
            const int k0 = (s + 1) * 32;
            const unsigned stg = sbase + ((s + 1) & 1) * 24576;
            #pragma unroll
            for (int i = 0; i < 4; i++) {
                int e = tid + i * 256;
                int r = e >> 3, g = e & 7;
                unsigned soff = (unsigned)(r * 128 + ((g ^ (r & 7)) << 4));
                const __nv_bfloat16* base = (g < 4) ? Ahi : Alo;
                cp16(stg + soff, base + (size_t)(m0 + r) * HH + k0 + (g & 3) * 8);
            }
            #pragma unroll
            for (int i = 0; i < 2; i++) {
                int e = tid + i * 256;
                int r = e >> 3, g = e & 7;
                unsigned soff = (unsigned)(r * 128 + ((g ^ (r & 7)) << 4));
                const __nv_bfloat16* base = (g < 4) ? Whi : Wlo;
                cp16(stg + 16384 + soff, base + (size_t)(n0 + r) * HH + k0 + (g & 3) * 8);
            }
            cp_commit();
            cp_wait<1>();
        } else {
            cp_wait<0>();
        }
        __syncthreads();

        const unsigned sA = sbase + (s & 1) * 24576;
        const unsigned sB = sA + 16384;

        #pragma unroll
        for (int kk = 0; kk < 2; kk++) {
            unsigned fAh[2][4], fAl[2][4], fBh[2][4], fBl[2][4];
            #pragma unroll
            for (int mt = 0; mt < 2; mt++) {
                int r = wm0 + mt * 16 + a_r;
                int ch = kk * 2 + a_kh;
                ldsm4(fAh[mt], sA + (unsigned)(r * 128 + ((ch ^ (r & 7)) << 4)));
                int cl = 4 + ch;
                ldsm4(fAl[mt], sA + (unsigned)(r * 128 + ((cl ^ (r & 7)) << 4)));
            }
            #pragma unroll
            for (int nt2 = 0; nt2 < 2; nt2++) {
                int r = wn0 + nt2 * 16 + b_r;
                int ch = kk * 2 + b_kh;
                ldsm4(fBh[nt2], sB + (unsigned)(r * 128 + ((ch ^ (r & 7)) << 4)));
                int cl = 4 + ch;
                ldsm4(fBl[nt2], sB + (unsigned)(r * 128 + ((cl ^ (r & 7)) << 4)));
            }
            #pragma unroll
            for (int mt = 0; mt < 2; mt++) {
                #pragma unroll
                for (int nt = 0; nt < 4; nt++) {
                    int n2 = nt >> 1, p = (nt & 1) * 2;
                    mma16816(acc[mt][nt], fAh[mt], fBh[n2][p], fBh[n2][p+1]);
                    mma16816(acc[mt][nt], fAh[mt], fBl[n2][p], fBl[n2][p+1]);
                    mma16816(acc[mt][nt], fAl[mt], fBh[n2][p], fBh[n2][p+1]);
                }
            }
        }
        __syncthreads();   // all reads of this stage done before it is reloaded
    }

    const int g = lane >> 2, q = lane & 3;
    #pragma unroll
    for (int mt = 0; mt < 2; mt++) {
        #pragma unroll
        for (int nt = 0; nt < 4; nt++) {
            int col = n0 + wn0 + nt * 8 + q * 2;
            float b0 = bias[col], b1 = bias[col + 1];
            #pragma unroll
            for (int half = 0; half < 2; half++) {
                int row = m0 + wm0 + mt * 16 + g + half * 8;
                float v0 = acc[mt][nt][half * 2]     + b0;
                float v1 = acc[mt][nt][half * 2 + 1] + b1;
                if (MODE == 0) {
                    *(float2*)&C[(size_t)row * HH + col] = make_float2(v0, v1);
                } else {
                    v0 *= oscale; v1 *= oscale;     // exact for powers of 2
                    int b = row >> 11, s = row & 2047;
                    int h = col >> 6,  d = col & 63;
                    size_t idx = (((size_t)(b * NH + h)) * SS + s) * HD + d;
                    __nv_bfloat162 hh = __float22bfloat162_rn(make_float2(v0, v1));
                    *(__nv_bfloat162*)&Chi[idx] = hh;
                    __nv_bfloat162 ll = __float22bfloat162_rn(make_float2(
                        v0 - __bfloat162float(hh.x), v1 - __bfloat162float(hh.y)));
                    *(__nv_bfloat162*)&Clo[idx] = ll;
                }
            }
        }
    }
}

// ---------------------------------------------------------------------------
// HMMA flash attention, bf16 split, 2-stage cp.async pipeline on K/V.
// Dynamic smem 64KB: buf(s) = s*32768; within: Khi 0 | Klo 8K | Vhi 16K | Vlo 24K.
// Q prologue stages through buf0 (hi at 0, lo at 16K), fragments -> registers.
// Q is pre-scaled by 1/sqrt(hd) at projection time.
// ---------------------------------------------------------------------------
__global__ __launch_bounds__(256)
void attn_mma_kernel()
{
    extern __shared__ __align__(128) char smd[];
    const unsigned sbase = (unsigned)__cvta_generic_to_shared(smd);

    const int tid  = threadIdx.x;
    const int lane = tid & 31;
    const int w    = tid >> 5;          // 0..7
    const int qt   = blockIdx.x;        // 0..15
    const int bh   = blockIdx.y;        // 0..31
    const size_t head_base = (size_t)bh * SS * HD;

    // ---- Stage Q tile (128 x 64 hi/lo) through buf0, pull fragments
    {
        const __nv_bfloat16* Qh = g_Qhi + head_base + (size_t)qt * 128 * HD;
        const __nv_bfloat16* Ql = g_Qlo + head_base + (size_t)qt * 128 * HD;
        #pragma unroll
        for (int i = 0; i < 4; i++) {
            int e = tid + i * 256;
            int r = e >> 3, c = e & 7;
            unsigned soff = (unsigned)(r * 128 + ((c ^ (r & 7)) << 4));
            cp16(sbase + soff,         Qh + (size_t)r * HD + c * 8);
            cp16(sbase + 16384 + soff, Ql + (size_t)r * HD + c * 8);
        }
        cp_commit();
        cp_wait<0>();
        __syncthreads();
    }

    const int a_r  = lane & 15;
    const int a_kh = lane >> 4;
    unsigned qh[4][4], ql[4][4];
    #pragma unroll
    for (int ks = 0; ks < 4; ks++) {
        int r = w * 16 + a_r;
        int c = ks * 2 + a_kh;
        unsigned off = (unsigned)(r * 128 + ((c ^ (r & 7)) << 4));
        ldsm4(qh[ks], sbase + off);
        ldsm4(ql[ks], sbase + 16384 + off);
    }
    __syncthreads();    // all Q fragments in registers before buf0 is reused

    float o[8][4] = {};
    float mrow[2] = {-1e30f, -1e30f};
    float lrow[2] = {0.0f, 0.0f};

    const int b_r  = (lane & 7) + ((lane >> 4) << 3);
    const int b_kh = (lane >> 3) & 1;
    const int NKT  = SS / 64;   // 32

    // ---- prologue: load K/V tile 0 into buf0
    {
        const size_t tb = head_base;
        const unsigned stg = sbase;
        #pragma unroll
        for (int i = 0; i < 2; i++) {
            int e = tid + i * 256;
            int r = e >> 3, c = e & 7;
            unsigned soff = (unsigned)(r * 128 + ((c ^ (r & 7)) << 4));
            size_t gi = tb + (size_t)r * HD + c * 8;
            cp16(stg + soff,         g_Khi + gi);
            cp16(stg +  8192 + soff, g_Klo + gi);
            cp16(stg + 16384 + soff, g_Vhi + gi);
            cp16(stg + 24576 + soff, g_Vlo + gi);
        }
        cp_commit();
    }

    for (int kt = 0; kt < NKT; kt++) {
        if (kt + 1 < NKT) {
            const size_t tb = head_base + (size_t)(kt + 1) * 64 * HD;
            const unsigned stg = sbase + ((kt + 1) & 1) * 32768;
            #pragma unroll
            for (int i = 0; i < 2; i++) {
                int e = tid + i * 256;
                int r = e >> 3, c = e & 7;
                unsigned soff = (unsigned)(r * 128 + ((c ^ (r & 7)) << 4));
                size_t gi = tb + (size_t)r * HD + c * 8;
                cp16(stg + soff,         g_Khi + gi);
                cp16(stg +  8192 + soff, g_Klo + gi);
                cp16(stg + 16384 + soff, g_Vhi + gi);
                cp16(stg + 24576 + soff, g_Vlo + gi);
            }
            cp_commit();
            cp_wait<1>();
        } else {
            cp_wait<0>();
        }
        __syncthreads();

        const unsigned sKhi = sbase + (kt & 1) * 32768;
        const unsigned sKlo = sKhi +  8192;
        const unsigned sVhi = sKhi + 16384;
        const unsigned sVlo = sKhi + 24576;

        // ---- S = Q K^T (m16 x n64), bf16 split 3-pass
        float sc[8][4] = {};
        #pragma unroll
        for (int ks = 0; ks < 4; ks++) {
            unsigned kh[4][4], kl[4][4];
            #pragma unroll
            for (int nt2 = 0; nt2 < 4; nt2++) {
                int r = nt2 * 16 + b_r;
                int c = ks * 2 + b_kh;
                unsigned off = (unsigned)(r * 128 + ((c ^ (r & 7)) << 4));
                ldsm4(kh[nt2], sKhi + off);
                ldsm4(kl[nt2], sKlo + off);
            }
            #pragma unroll
            for (int nt = 0; nt < 8; nt++) {
                int n2 = nt >> 1, p = (nt & 1) * 2;
                mma16816(sc[nt], qh[ks], kh[n2][p], kh[n2][p+1]);
                mma16816(sc[nt], qh[ks], kl[n2][p], kl[n2][p+1]);
                mma16816(sc[nt], ql[ks], kh[n2][p], kh[n2][p+1]);
            }
        }

        // ---- online softmax on fragment rows (g and g+8); Q pre-scaled
        #pragma unroll
        for (int rr = 0; rr < 2; rr++) {
            const int base = rr * 2;
            float tm = -1e30f;
            #pragma unroll
            for (int nt = 0; nt < 8; nt++)
                tm = fmaxf(tm, fmaxf(sc[nt][base], sc[nt][base + 1]));
            tm = fmaxf(tm, __shfl_xor_sync(0xffffffffu, tm, 1));
            tm = fmaxf(tm, __shfl_xor_sync(0xffffffffu, tm, 2));
            float mn   = fmaxf(mrow[rr], tm);
            float corr = __expf(mrow[rr] - mn);
            mrow[rr] = mn;
            float rs = 0.0f;
            #pragma unroll
            for (int nt = 0; nt < 8; nt++) {
                float p0 = __expf(sc[nt][base]     - mn);
                float p1 = __expf(sc[nt][base + 1] - mn);
                sc[nt][base] = p0; sc[nt][base + 1] = p1;
                rs += p0 + p1;
            }
            rs += __shfl_xor_sync(0xffffffffu, rs, 1);
            rs += __shfl_xor_sync(0xffffffffu, rs, 2);
            lrow[rr] = lrow[rr] * corr + rs;
            #pragma unroll
            for (int nt = 0; nt < 8; nt++) {
                o[nt][base]     *= corr;
                o[nt][base + 1] *= corr;
            }
        }

        // ---- O += P V (P re-packed in regs, split hi/lo; V via ldmatrix.trans)
        #pragma unroll
        for (int ks2 = 0; ks2 < 4; ks2++) {
            unsigned phi[4], plo[4];
            #pragma unroll
            for (int part = 0; part < 2; part++) {
                int nt = 2 * ks2 + part;
                #pragma unroll
                for (int hh = 0; hh < 2; hh++) {
                    float p0 = sc[nt][hh * 2], p1 = sc[nt][hh * 2 + 1];
                    __nv_bfloat162 h2 = __float22bfloat162_rn(make_float2(p0, p1));
                    phi[part * 2 + hh] = *(unsigned*)&h2;
                    plo[part * 2 + hh] = pack_bf(p0 - __bfloat162float(h2.x),
                                                 p1 - __bfloat162float(h2.y));
                }
            }
            #pragma unroll
            for (int dt = 0; dt < 4; dt++) {
                int r = ks2 * 16 + (lane & 15);
                int c = dt * 2 + (lane >> 4);
                unsigned off = (unsigned)(r * 128 + ((c ^ (r & 7)) << 4));
                unsigned vh[4], vl[4];
                ldsm4t(vh, sVhi + off);
                ldsm4t(vl, sVlo + off);
                mma16816(o[2*dt],     phi, vh[0], vh[1]);
                mma16816(o[2*dt],     phi, vl[0], vl[1]);
                mma16816(o[2*dt],     plo, vh[0], vh[1]);
                mma16816(o[2*dt + 1], phi, vh[2], vh[3]);
                mma16816(o[2*dt + 1], phi, vl[2], vl[3]);
                mma16816(o[2*dt + 1], plo, vh[2], vh[3]);
            }
        }
        __syncthreads();   // stage fully consumed before its buffer reloads
    }

    // ---- epilogue: normalize, write bf16 hi/lo into GEMM-A staging [B,S,H]
    const int b = bh >> 4, h = bh & 15;
    const int g = lane >> 2, q = lane & 3;
    const float inv0 = 1.0f / lrow[0];
    const float inv1 = 1.0f / lrow[1];
    const int row0 = qt * 128 + w * 16 + g;
    #pragma unroll
    for (int nt = 0; nt < 8; nt++) {
        int d = h * 64 + nt * 8 + q * 2;
        size_t i0 = ((size_t)(b * SS + row0))     * HH + d;
        size_t i1 = ((size_t)(b * SS + row0 + 8)) * HH + d;
        float v0 = o[nt][0] * inv0, v1 = o[nt][1] * inv0;
        float v2 = o[nt][2] * inv1, v3 = o[nt][3] * inv1;
        __nv_bfloat162 h2a = __float22bfloat162_rn(make_float2(v0, v1));
        *(__nv_bfloat162*)&g_Ahi[i0] = h2a;
        *(__nv_bfloat162*)&g_Alo[i0] = __float22bfloat162_rn(make_float2(
            v0 - __bfloat162float(h2a.x), v1 - __bfloat162float(h2a.y)));
        __nv_bfloat162 h2b = __float22bfloat162_rn(make_float2(v2, v3));
        *(__nv_bfloat162*)&g_Ahi[i1] = h2b;
        *(__nv_bfloat162*)&g_Alo[i1] = __float22bfloat162_rn(make_float2(
            v2 - __bfloat162float(h2b.x), v3 - __bfloat162float(h2b.y)));
    }
}

// ---------------------------------------------------------------------------
extern "C" void kernel_launch(void* const* d_in, const int* in_sizes, int n_in,
                              void* d_out, int out_size)
{
    const float* q  = (const float*)d_in[0];
    const float* k  = (const float*)d_in[1];
    const float* v  = (const float*)d_in[2];
    const float* Wq = (const float*)d_in[3];
    const float* bq = (const float*)d_in[4];
    const float* Wk = (const float*)d_in[5];
    const float* bk = (const float*)d_in[6];
    const float* Wv = (const float*)d_in[7];
    const float* bv = (const float*)d_in[8];
    const float* Wo = (const float*)d_in[9];
    const float* bo = (const float*)d_in[10];
    float* out = (float*)d_out;

    __nv_bfloat16 *Qhi, *Qlo, *Khi, *Klo, *Vhi, *Vlo, *Ahi, *Alo, *Whi, *Wlo;
    cudaGetSymbolAddress((void**)&Qhi, g_Qhi);
    cudaGetSymbolAddress((void**)&Qlo, g_Qlo);
    cudaGetSymbolAddress((void**)&Khi, g_Khi);
    cudaGetSymbolAddress((void**)&Klo, g_Klo);
    cudaGetSymbolAddress((void**)&Vhi, g_Vhi);
    cudaGetSymbolAddress((void**)&Vlo, g_Vlo);
    cudaGetSymbolAddress((void**)&Ahi, g_Ahi);
    cudaGetSymbolAddress((void**)&Alo, g_Alo);
    cudaGetSymbolAddress((void**)&Whi, g_Whi);
    cudaGetSymbolAddress((void**)&Wlo, g_Wlo);

    cudaFuncSetAttribute(attn_mma_kernel,
                         cudaFuncAttributeMaxDynamicSharedMemorySize, 65536);

    const int CVT_A_BLOCKS = (MTOT * HH / 4) / 256;  // 4096
    const int CVT_W_BLOCKS = (HH * HH / 4) / 256;    // 1024
    dim3 blk(256);
    dim3 gg(HH / 64, MTOT / 128);                    // (16, 32)

    // Q projection -> bf16 split heads, pre-scaled by 1/sqrt(64)
    cvt_split_kernel<<<CVT_A_BLOCKS, blk>>>(q, Ahi, Alo);
    cvt_split_kernel<<<CVT_W_BLOCKS, blk>>>(Wq, Whi, Wlo);
    gemm_mma_kernel<1><<<gg, blk>>>(Ahi, Alo, Whi, Wlo, bq, nullptr, Qhi, Qlo, 0.125f);
    // K projection
    cvt_split_kernel<<<CVT_A_BLOCKS, blk>>>(k, Ahi, Alo);
    cvt_split_kernel<<<CVT_W_BLOCKS, blk>>>(Wk, Whi, Wlo);
    gemm_mma_kernel<1><<<gg, blk>>>(Ahi, Alo, Whi, Wlo, bk, nullptr, Khi, Klo, 1.0f);
    // V projection
    cvt_split_kernel<<<CVT_A_BLOCKS, blk>>>(v, Ahi, Alo);
    cvt_split_kernel<<<CVT_W_BLOCKS, blk>>>(Wv, Whi, Wlo);
    gemm_mma_kernel<1><<<gg, blk>>>(Ahi, Alo, Whi, Wlo, bv, nullptr, Vhi, Vlo, 1.0f);
    // Attention (writes O as bf16 split directly into Ahi/Alo)
    attn_mma_kernel<<<dim3(SS / 128, BB * NH), blk, 65536>>>();
    // Output projection
    cvt_split_kernel<<<CVT_W_BLOCKS, blk>>>(Wo, Whi, Wlo);
    gemm_mma_kernel<0><<<gg, blk>>>(Ahi, Alo, Whi, Wlo, bo, out, nullptr, nullptr, 1.0f);
}